// round 2
// baseline (speedup 1.0000x reference)
#include <cuda_runtime.h>
#include <cstdint>
#include <cstddef>

#define D_TONES 88
#define T_LEN   512
#define K2ST    256
#define BATCH   1024
#define TILE_T  64
#define NTILES  8

typedef unsigned long long u64t;

// ---------------- device scratch ----------------
__device__ float g_wd[D_TONES * K2ST];                  // (logp - log1mp), [d][k]
__device__ float g_cst[K2ST];                           // sum_d log1mp
__device__ float g_la0[K2ST];                           // log init joint
__device__ float g_logB[(size_t)BATCH * TILE_T * K2ST]; // 64 MB tile scratch (L2-resident)
__device__ float g_m[BATCH * TILE_T];                   // per-(b,t) max_k logB
__device__ float g_alpha[BATCH * K2ST];                 // linear alpha carry
__device__ float g_C[BATCH];                            // log-scale accumulator
__device__ float g_part[BATCH];

// ---------------- f32x2 helpers ----------------
#define FMA2(acc, a, b) asm("fma.rn.f32x2 %0,%1,%2,%0;" : "+l"(acc) : "l"(a), "l"(b))
#define DUP2(dst, s)    asm("mov.b64 %0,{%1,%1};" : "=l"(dst) : "f"(s))
#define UNPK(lo, hi, v) asm("mov.b64 {%0,%1},%2;" : "=f"(lo), "=f"(hi) : "l"(v))

// ---------------- warp reductions ----------------
__device__ __forceinline__ float warpMaxf(float v) {
#pragma unroll
    for (int s = 16; s > 0; s >>= 1) v = fmaxf(v, __shfl_xor_sync(0xffffffffu, v, s));
    return v;
}
__device__ __forceinline__ float warpSumf(float v) {
#pragma unroll
    for (int s = 16; s > 0; s >>= 1) v += __shfl_xor_sync(0xffffffffu, v, s);
    return v;
}

// ---------------- K0: precompute ----------------
__global__ void k0_setup(const float* __restrict__ probs_y,
                         const float* __restrict__ w_init,
                         const float* __restrict__ x_init) {
    int k = threadIdx.x;  // 256
    float cs = 0.0f;
    for (int d = 0; d < D_TONES; d++) {
        float py = probs_y[k * D_TONES + d];
        float l1 = log1pf(-py);
        g_wd[d * K2ST + k] = logf(py) - l1;
        cs += l1;
    }
    g_cst[k] = cs;
    g_la0[k] = logf(w_init[k >> 4]) + logf(x_init[k & 15]);
}

// ---------------- K1: emission GEMM (f32x2), 64t x 64k per block ----------------
__global__ void __launch_bounds__(128) k1_emis(const float* __restrict__ seq,
                                               const int* __restrict__ lengths,
                                               const int* __restrict__ mb,
                                               int tile) {
    const int b  = blockIdx.x;
    const int kq = blockIdx.y;            // 0..3 -> 64 k-cols
    const int t0 = tile * TILE_T;
    const int row = __ldg(&mb[b]);
    const int len = __ldg(&lengths[row]);
    if (t0 >= len) return;

    __shared__ __align__(16) float Ssm[D_TONES][68];   // transposed seq [d][t]
    __shared__ __align__(16) float Wsm[D_TONES][64];   // weights [d][kc]

    const int tid = threadIdx.x;
    {
        const float* sp = seq + ((size_t)row * T_LEN + t0) * D_TONES;
        for (int idx = tid; idx < 64 * 22; idx += 128) {
            int r = idx / 22, c = idx % 22;
            float4 v = *reinterpret_cast<const float4*>(sp + (size_t)r * D_TONES + c * 4);
            Ssm[c * 4 + 0][r] = v.x;
            Ssm[c * 4 + 1][r] = v.y;
            Ssm[c * 4 + 2][r] = v.z;
            Ssm[c * 4 + 3][r] = v.w;
        }
        const float* wp = g_wd + kq * 64;
        for (int idx = tid; idx < D_TONES * 16; idx += 128) {
            int d = idx >> 4, c = idx & 15;
            *reinterpret_cast<float4*>(&Wsm[d][c * 4]) =
                *reinterpret_cast<const float4*>(wp + (size_t)d * K2ST + c * 4);
        }
    }
    __syncthreads();

    const int rr = tid >> 3;   // 0..15 -> rows rr*4
    const int cc = tid & 7;    // 0..7  -> cols cc*8
    u64t acc[4][4];
#pragma unroll
    for (int i = 0; i < 4; i++)
#pragma unroll
        for (int p = 0; p < 4; p++) acc[i][p] = 0ull;

    const unsigned waddr = (unsigned)__cvta_generic_to_shared(&Wsm[0][cc * 8]);
    const float* srow = &Ssm[0][rr * 4];

#pragma unroll 4
    for (int d = 0; d < D_TONES; d++) {
        float4 s4 = *reinterpret_cast<const float4*>(srow + d * 68);
        u64t w01, w23, w45, w67;
        asm("ld.shared.v2.u64 {%0,%1},[%2];" : "=l"(w01), "=l"(w23) : "r"(waddr + d * 256));
        asm("ld.shared.v2.u64 {%0,%1},[%2];" : "=l"(w45), "=l"(w67) : "r"(waddr + d * 256 + 16));
        u64t sx;
        DUP2(sx, s4.x);
        FMA2(acc[0][0], sx, w01); FMA2(acc[0][1], sx, w23);
        FMA2(acc[0][2], sx, w45); FMA2(acc[0][3], sx, w67);
        DUP2(sx, s4.y);
        FMA2(acc[1][0], sx, w01); FMA2(acc[1][1], sx, w23);
        FMA2(acc[1][2], sx, w45); FMA2(acc[1][3], sx, w67);
        DUP2(sx, s4.z);
        FMA2(acc[2][0], sx, w01); FMA2(acc[2][1], sx, w23);
        FMA2(acc[2][2], sx, w45); FMA2(acc[2][3], sx, w67);
        DUP2(sx, s4.w);
        FMA2(acc[3][0], sx, w01); FMA2(acc[3][1], sx, w23);
        FMA2(acc[3][2], sx, w45); FMA2(acc[3][3], sx, w67);
    }

    float cA[8];
    *reinterpret_cast<float4*>(&cA[0]) = *reinterpret_cast<const float4*>(g_cst + kq * 64 + cc * 8);
    *reinterpret_cast<float4*>(&cA[4]) = *reinterpret_cast<const float4*>(g_cst + kq * 64 + cc * 8 + 4);

#pragma unroll
    for (int i = 0; i < 4; i++) {
        float o[8];
#pragma unroll
        for (int p = 0; p < 4; p++) UNPK(o[2 * p], o[2 * p + 1], acc[i][p]);
        float4 lo, hi;
        lo.x = o[0] + cA[0]; lo.y = o[1] + cA[1]; lo.z = o[2] + cA[2]; lo.w = o[3] + cA[3];
        hi.x = o[4] + cA[4]; hi.y = o[5] + cA[5]; hi.z = o[6] + cA[6]; hi.w = o[7] + cA[7];
        size_t off = ((size_t)b * TILE_T + rr * 4 + i) * K2ST + kq * 64 + cc * 8;
        *reinterpret_cast<float4*>(g_logB + off)     = lo;
        *reinterpret_cast<float4*>(g_logB + off + 4) = hi;
    }
}

// ---------------- K1b: per-(b,t) max over k (one block per b) ----------------
__global__ void __launch_bounds__(256) k1b_max() {
    const int b = blockIdx.x;
    const int wid = threadIdx.x >> 5;
    const int lane = threadIdx.x & 31;
#pragma unroll
    for (int it = 0; it < 8; it++) {
        int t = wid * 8 + it;
        const float* p = g_logB + ((size_t)b * TILE_T + t) * K2ST;
        float v = -3.4e38f;
#pragma unroll
        for (int k = 0; k < 8; k++) v = fmaxf(v, p[lane + 32 * k]);
        v = warpMaxf(v);
        if (lane == 0) g_m[b * TILE_T + t] = v;
    }
}

// ---------------- K2: forward recursion, register alpha, 1 sync/step ----------------
__global__ void __launch_bounds__(256, 6) k2_fwd(const float* __restrict__ probs_w,
                                                 const float* __restrict__ probs_x,
                                                 const int* __restrict__ lengths,
                                                 const int* __restrict__ mb,
                                                 int tile) {
    const int b = blockIdx.x;
    const int t0 = tile * TILE_T;
    const int len = __ldg(&lengths[__ldg(&mb[b])]);
    if (t0 >= len) return;

    __shared__ __align__(16) float tmp_s[2][16 * 18];  // transposed, pad 18: idx = j*18 + w
    __shared__ __align__(8)  float2 Wp_s[8][16];       // Wp_s[p][i] = (W[2p][i], W[2p+1][i])
    __shared__ float m_s[TILE_T];
    __shared__ float red[8];

    const int tid = threadIdx.x;
    const int i = tid >> 4;     // w / w'
    const int j = tid & 15;     // x'
    const int lane = tid & 31;
    const int w0 = tid >> 5;

    float Xc[16];
#pragma unroll
    for (int x = 0; x < 16; x++) Xc[x] = __ldg(&probs_x[x * 16 + j]);
    if (tid < 128) {
        int p = tid >> 4, ii = tid & 15;
        Wp_s[p][ii] = make_float2(__ldg(&probs_w[(2 * p) * 16 + ii]),
                                  __ldg(&probs_w[(2 * p + 1) * 16 + ii]));
    }
    if (tid < TILE_T) m_s[tid] = g_m[b * TILE_T + tid];

    const float* lb = g_logB + (size_t)b * TILE_T * K2ST;
    float a, C;
    int tl_start;
    if (tile == 0) {
        float v = g_la0[tid] + lb[tid];
        float mv = warpMaxf(v);
        if (lane == 0) red[w0] = mv;
        __syncthreads();
        float mx = red[0];
#pragma unroll
        for (int w = 1; w < 8; w++) mx = fmaxf(mx, red[w]);
        a = __expf(v - mx);
        C = mx;
        tl_start = 1;
    } else {
        a = g_alpha[b * K2ST + tid];
        C = g_C[b];
        tl_start = 0;
        __syncthreads();
    }

    const int tl_end = min(TILE_T, len - t0);
    const unsigned tw = (unsigned)__cvta_generic_to_shared(&tmp_s[0][j * 18 + i]);
    const unsigned tr = (unsigned)__cvta_generic_to_shared(&tmp_s[0][j * 18]);
    const unsigned wp = (unsigned)__cvta_generic_to_shared(&Wp_s[0][i]);
    const unsigned bstr = 16 * 18 * 4;
    const int base = lane & 16;
    unsigned boff = 0;

    for (int tl = tl_start; tl < tl_end; ++tl) {
        float bv = lb[(size_t)tl * K2ST + tid];

        // step1: tmp[i][j] = sum_x A[i][x] * X[x][j] via warp shuffles
        float s0 = 0.0f, s1 = 0.0f;
#pragma unroll
        for (int x = 0; x < 16; x += 2) {
            s0 = fmaf(__shfl_sync(0xffffffffu, a, base | x),       Xc[x],     s0);
            s1 = fmaf(__shfl_sync(0xffffffffu, a, base | (x + 1)), Xc[x + 1], s1);
        }
        float tv = s0 + s1;
        asm volatile("st.shared.f32 [%0], %1;" :: "r"(tw + boff), "f"(tv));
        __syncthreads();

        // step2: an = (sum_w W[w][i] * tmp[w][j]) * exp(bv - m)  (f32x2 pairs)
        u64t acc = 0ull;
#pragma unroll
        for (int p = 0; p < 8; p++) {
            u64t t2, w2;
            asm("ld.shared.b64 %0,[%1];" : "=l"(t2) : "r"(tr + boff + p * 8));
            asm("ld.shared.b64 %0,[%1];" : "=l"(w2) : "r"(wp + p * 128));
            FMA2(acc, t2, w2);
        }
        float r0, r1;
        UNPK(r0, r1, acc);
        float e = __expf(bv - m_s[tl]);
        a = (r0 + r1) * e;
        C += m_s[tl];

        if (((t0 + tl) & 3) == 3) {   // renorm every 4 steps (validated R1)
            float vs = warpSumf(a);
            if (lane == 0) red[w0] = vs;
            __syncthreads();
            float ss = red[0];
#pragma unroll
            for (int w = 1; w < 8; w++) ss += red[w];
            a *= 1.0f / ss;
            C += __logf(ss);
        }
        boff ^= bstr;
    }

    g_alpha[b * K2ST + tid] = a;
    if (tid == 0) g_C[b] = C;
}

// ---------------- K3: per-b loglik ----------------
__global__ void k3_loglik() {
    __shared__ float red[8];
    const int b = blockIdx.x;
    const int lane = threadIdx.x & 31;
    const int w0 = threadIdx.x >> 5;
    float v = g_alpha[b * K2ST + threadIdx.x];
    v = warpSumf(v);
    if (lane == 0) red[w0] = v;
    __syncthreads();
    if (threadIdx.x == 0) {
        float s = red[0];
#pragma unroll
        for (int w = 1; w < 8; w++) s += red[w];
        g_part[b] = g_C[b] + logf(s);
    }
}

// ---------------- K4: final sum ----------------
__global__ void k4_sum(float* __restrict__ out) {
    __shared__ float red[8];
    const int lane = threadIdx.x & 31;
    const int w0 = threadIdx.x >> 5;
    float acc = 0.0f;
    for (int idx = threadIdx.x; idx < BATCH; idx += 256) acc += g_part[idx];
    acc = warpSumf(acc);
    if (lane == 0) red[w0] = acc;
    __syncthreads();
    if (threadIdx.x == 0) {
        float s = red[0];
#pragma unroll
        for (int w = 1; w < 8; w++) s += red[w];
        out[0] = s;
    }
}

// ---------------- launch ----------------
extern "C" void kernel_launch(void* const* d_in, const int* in_sizes, int n_in,
                              void* d_out, int out_size) {
    const float* seq     = (const float*)d_in[0];
    const float* probs_w = (const float*)d_in[1];
    const float* probs_x = (const float*)d_in[2];
    const float* w_init  = (const float*)d_in[3];
    const float* x_init  = (const float*)d_in[4];
    const float* probs_y = (const float*)d_in[5];
    const int*   lengths = (const int*)d_in[6];
    const int*   mb      = (const int*)d_in[7];
    float* out = (float*)d_out;

    k0_setup<<<1, 256>>>(probs_y, w_init, x_init);
    for (int tile = 0; tile < NTILES; tile++) {
        k1_emis<<<dim3(BATCH, 4), 128>>>(seq, lengths, mb, tile);
        k1b_max<<<BATCH, 256>>>();
        k2_fwd<<<BATCH, 256>>>(probs_w, probs_x, lengths, mb, tile);
    }
    k3_loglik<<<BATCH, 256>>>();
    k4_sum<<<1, 256>>>(out);
}

// round 3
// speedup vs baseline: 1.7688x; 1.7688x over previous
#include <cuda_runtime.h>
#include <cuda_fp16.h>
#include <cstdint>
#include <cstddef>

#define D_TONES 88
#define DPAD    104          // padded K (88->96 compute, 104 stride: conflict-free)
#define T_LEN   512
#define K2ST    256
#define BATCH   1024
#define TILE_T  64
#define NTILES  8

typedef unsigned long long u64t;

// ---------------- device scratch ----------------
__device__ __align__(16) __half g_wdh[K2ST * DPAD];     // fp16 weights [k][d], padded
__device__ float g_cst[K2ST];                           // sum_d log1mp
__device__ float g_a0[K2ST];                            // linear init w_init*x_init
__device__ float g_logB[(size_t)BATCH * TILE_T * K2ST]; // logB, then E in place
__device__ float g_msum[BATCH];                         // per-tile sum of row maxes
__device__ float g_alpha[BATCH * K2ST];
__device__ float g_C[BATCH];
__device__ float g_part[BATCH];

// ---------------- helpers ----------------
#define FMA2(acc, a, b) asm("fma.rn.f32x2 %0,%1,%2,%0;" : "+l"(acc) : "l"(a), "l"(b))
#define UNPK(lo, hi, v) asm("mov.b64 {%0,%1},%2;" : "=f"(lo), "=f"(hi) : "l"(v))

__device__ __forceinline__ unsigned smem_u32(const void* p) {
    return (unsigned)__cvta_generic_to_shared(p);
}
__device__ __forceinline__ float warpMaxf(float v) {
#pragma unroll
    for (int s = 16; s > 0; s >>= 1) v = fmaxf(v, __shfl_xor_sync(0xffffffffu, v, s));
    return v;
}
__device__ __forceinline__ float warpSumf(float v) {
#pragma unroll
    for (int s = 16; s > 0; s >>= 1) v += __shfl_xor_sync(0xffffffffu, v, s);
    return v;
}

// ---------------- K0: precompute ----------------
__global__ void k0_setup(const float* __restrict__ probs_y,
                         const float* __restrict__ w_init,
                         const float* __restrict__ x_init) {
    int k = threadIdx.x;  // 256
    float cs = 0.0f;
    for (int d = 0; d < DPAD; d++) {
        float w = 0.0f;
        if (d < D_TONES) {
            float py = probs_y[k * D_TONES + d];
            float l1 = log1pf(-py);
            w = logf(py) - l1;
            cs += l1;
        }
        g_wdh[k * DPAD + d] = __float2half_rn(w);
    }
    g_cst[k] = cs;
    g_a0[k] = w_init[k >> 4] * x_init[k & 15];
}

// ---------------- K1: emission GEMM via mma.sync (64t x 128k per block) ----------------
__global__ void __launch_bounds__(256) k1_emis(const float* __restrict__ seq,
                                               const int* __restrict__ lengths,
                                               const int* __restrict__ mb,
                                               int tile) {
    const int b   = blockIdx.x;
    const int nh2 = blockIdx.y;             // 0/1: state half
    const int t0  = tile * TILE_T;
    const int row = __ldg(&mb[b]);
    const int len = __ldg(&lengths[row]);
    if (t0 >= len) return;

    __shared__ __align__(16) __half Asm[TILE_T][DPAD];  // seq tile fp16
    __shared__ __align__(16) __half Bsm[128][DPAD];     // weight half

    const int tid = threadIdx.x;
    // B: flat copy of g_wdh half (layout identical, 16B vectors)
    const uint4* wp = reinterpret_cast<const uint4*>(g_wdh + (size_t)nh2 * 128 * DPAD);
    for (int idx = tid; idx < 128 * 13; idx += 256)
        reinterpret_cast<uint4*>(&Bsm[0][0])[idx] = __ldg(&wp[idx]);
    // zero A pad cols 88..103
    for (int idx = tid; idx < TILE_T * 2; idx += 256) {
        int r = idx >> 1, q = idx & 1;
        *reinterpret_cast<uint4*>(&Asm[r][88 + q * 8]) = make_uint4(0, 0, 0, 0);
    }
    // A: load f32, convert to fp16
    const float4* sp = reinterpret_cast<const float4*>(seq + ((size_t)row * T_LEN + t0) * D_TONES);
    for (int idx = tid; idx < TILE_T * 22; idx += 256) {
        int r = idx / 22, c4 = idx % 22;
        float4 v = __ldg(&sp[(size_t)r * 22 + c4]);
        __half2 h0 = __floats2half2_rn(v.x, v.y);
        __half2 h1 = __floats2half2_rn(v.z, v.w);
        uint2 u;
        u.x = *reinterpret_cast<unsigned*>(&h0);
        u.y = *reinterpret_cast<unsigned*>(&h1);
        *reinterpret_cast<uint2*>(&Asm[r][c4 * 4]) = u;
    }
    __syncthreads();

    const int w = tid >> 5, lane = tid & 31;
    const int mt = w & 3;                 // row tile (16 rows)
    const int nh = (w >> 2) * 64;         // col offset within 128

    float c[8][4];
#pragma unroll
    for (int q = 0; q < 8; q++) { c[q][0] = c[q][1] = c[q][2] = c[q][3] = 0.0f; }

    const unsigned aBase = smem_u32(&Asm[mt * 16 + (lane & 15)][(lane >> 4) * 8]);
    const unsigned bBase = smem_u32(&Bsm[nh + ((lane >> 4) * 8) + (lane & 7)][((lane >> 3) & 1) * 8]);

#pragma unroll
    for (int ks = 0; ks < 6; ks++) {
        unsigned a0, a1, a2, a3;
        asm volatile("ldmatrix.sync.aligned.m8n8.x4.shared.b16 {%0,%1,%2,%3},[%4];"
                     : "=r"(a0), "=r"(a1), "=r"(a2), "=r"(a3) : "r"(aBase + ks * 32));
#pragma unroll
        for (int nt2 = 0; nt2 < 4; nt2++) {
            unsigned b0, b1, b2, b3;
            asm volatile("ldmatrix.sync.aligned.m8n8.x4.shared.b16 {%0,%1,%2,%3},[%4];"
                         : "=r"(b0), "=r"(b1), "=r"(b2), "=r"(b3)
                         : "r"(bBase + nt2 * (16 * DPAD * 2) + ks * 32));
            asm volatile("mma.sync.aligned.m16n8k16.row.col.f32.f16.f16.f32 "
                         "{%0,%1,%2,%3},{%4,%5,%6,%7},{%8,%9},{%0,%1,%2,%3};"
                         : "+f"(c[nt2 * 2][0]), "+f"(c[nt2 * 2][1]),
                           "+f"(c[nt2 * 2][2]), "+f"(c[nt2 * 2][3])
                         : "r"(a0), "r"(a1), "r"(a2), "r"(a3), "r"(b0), "r"(b1));
            asm volatile("mma.sync.aligned.m16n8k16.row.col.f32.f16.f16.f32 "
                         "{%0,%1,%2,%3},{%4,%5,%6,%7},{%8,%9},{%0,%1,%2,%3};"
                         : "+f"(c[nt2 * 2 + 1][0]), "+f"(c[nt2 * 2 + 1][1]),
                           "+f"(c[nt2 * 2 + 1][2]), "+f"(c[nt2 * 2 + 1][3])
                         : "r"(a0), "r"(a1), "r"(a2), "r"(a3), "r"(b2), "r"(b3));
        }
    }

    // epilogue: + cst, store f32
    const int r0 = mt * 16 + (lane >> 2);
    const int cb = nh2 * 128 + nh;
    const int cl = 2 * (lane & 3);
    const size_t ro0 = ((size_t)b * TILE_T + r0) * K2ST;
    const size_t ro1 = ro0 + 8 * K2ST;
#pragma unroll
    for (int q = 0; q < 8; q++) {
        int colg = cb + q * 8 + cl;
        float2 cst2 = *reinterpret_cast<const float2*>(&g_cst[colg]);
        float2 o0 = make_float2(c[q][0] + cst2.x, c[q][1] + cst2.y);
        float2 o1 = make_float2(c[q][2] + cst2.x, c[q][3] + cst2.y);
        *reinterpret_cast<float2*>(&g_logB[ro0 + colg]) = o0;
        *reinterpret_cast<float2*>(&g_logB[ro1 + colg]) = o1;
    }
}

// ---------------- K1b: row max + in-place E=exp(logB-m) + tile sum of m ----------------
__global__ void __launch_bounds__(256) k1b_maxexp(const int* __restrict__ lengths,
                                                  const int* __restrict__ mb, int tile) {
    const int b = blockIdx.x;
    const int t0 = tile * TILE_T;
    const int len = __ldg(&lengths[__ldg(&mb[b])]);
    if (t0 >= len) return;
    __shared__ float m_sh[TILE_T];
    const int wid = threadIdx.x >> 5, lane = threadIdx.x & 31;
#pragma unroll
    for (int it = 0; it < 8; it++) {
        int t = wid * 8 + it;
        float* p = g_logB + ((size_t)b * TILE_T + t) * K2ST;
        float v[8];
#pragma unroll
        for (int q = 0; q < 8; q++) v[q] = p[lane + 32 * q];
        float mx = v[0];
#pragma unroll
        for (int q = 1; q < 8; q++) mx = fmaxf(mx, v[q]);
        mx = warpMaxf(mx);
#pragma unroll
        for (int q = 0; q < 8; q++) p[lane + 32 * q] = __expf(v[q] - mx);
        if (lane == 0) m_sh[t] = mx;
    }
    __syncthreads();
    if (threadIdx.x < 32) {
        int end = min(TILE_T, len - t0);
        float s = (lane < end ? m_sh[lane] : 0.0f) +
                  (32 + lane < end ? m_sh[32 + lane] : 0.0f);
        s = warpSumf(s);
        if (lane == 0) g_msum[b] = s;
    }
}

// ---------------- K2: forward recursion (linear space, E precomputed) ----------------
__global__ void __launch_bounds__(256, 5) k2_fwd(const float* __restrict__ probs_w,
                                                 const float* __restrict__ probs_x,
                                                 const int* __restrict__ lengths,
                                                 const int* __restrict__ mb,
                                                 int tile) {
    const int b = blockIdx.x;
    const int t0 = tile * TILE_T;
    const int len = __ldg(&lengths[__ldg(&mb[b])]);
    if (t0 >= len) return;

    __shared__ __align__(16) float tmp_s[2][16 * 18];  // [j*18 + w], pad 18
    __shared__ float red[8];

    const int tid = threadIdx.x;
    const int i = tid >> 4;     // w / w'
    const int j = tid & 15;     // x'
    const int lane = tid & 31;
    const int w0 = tid >> 5;

    float Xc[16];
#pragma unroll
    for (int x = 0; x < 16; x++) Xc[x] = __ldg(&probs_x[x * 16 + j]);
    u64t Wpk[8];                // packed (W[2p][i], W[2p+1][i]) — register-resident
#pragma unroll
    for (int p = 0; p < 8; p++) {
        float wa = __ldg(&probs_w[(2 * p) * 16 + i]);
        float wb = __ldg(&probs_w[(2 * p + 1) * 16 + i]);
        asm("mov.b64 %0,{%1,%2};" : "=l"(Wpk[p]) : "f"(wa), "f"(wb));
    }

    const float* lb = g_logB + (size_t)b * TILE_T * K2ST;   // E values
    float a, C;
    int tl_start;
    if (tile == 0) {
        a = g_a0[tid] * lb[tid];          // linear init; C starts at tile msum (incl m0)
        C = g_msum[b];
        tl_start = 1;
    } else {
        a = g_alpha[b * K2ST + tid];
        C = g_C[b] + g_msum[b];
        tl_start = 0;
    }

    const int tl_end = min(TILE_T, len - t0);
    const unsigned tw = smem_u32(&tmp_s[0][j * 18 + i]);
    const unsigned tr = smem_u32(&tmp_s[0][j * 18]);
    const unsigned bstr = 16 * 18 * 4;
    const int base = lane & 16;
    unsigned boff = 0;

    for (int tl = tl_start; tl < tl_end; ++tl) {
        float e = lb[(size_t)tl * K2ST + tid];

        // step1: tmp[i][j] = sum_x A[i][x] * X[x][j] via warp shuffles
        float s0 = 0.0f, s1 = 0.0f;
#pragma unroll
        for (int x = 0; x < 16; x += 2) {
            s0 = fmaf(__shfl_sync(0xffffffffu, a, base | x),       Xc[x],     s0);
            s1 = fmaf(__shfl_sync(0xffffffffu, a, base | (x + 1)), Xc[x + 1], s1);
        }
        float tv = s0 + s1;
        asm volatile("st.shared.f32 [%0], %1;" :: "r"(tw + boff), "f"(tv));
        __syncthreads();

        // step2: a' = (sum_w W[w][i] * tmp[w][j]) * E   (f32x2, W in regs)
        u64t acc = 0ull;
#pragma unroll
        for (int p = 0; p < 8; p++) {
            u64t t2;
            asm("ld.shared.b64 %0,[%1];" : "=l"(t2) : "r"(tr + boff + p * 8));
            FMA2(acc, t2, Wpk[p]);
        }
        float r0, r1;
        UNPK(r0, r1, acc);
        a = (r0 + r1) * e;

        if (((t0 + tl) & 3) == 3) {   // renorm every 4 steps (validated R1/R2)
            float vs = warpSumf(a);
            if (lane == 0) red[w0] = vs;
            __syncthreads();
            float ss = red[0];
#pragma unroll
            for (int ww = 1; ww < 8; ww++) ss += red[ww];
            a *= 1.0f / ss;
            C += __logf(ss);
        }
        boff ^= bstr;
    }

    g_alpha[b * K2ST + tid] = a;
    if (tid == 0) g_C[b] = C;
}

// ---------------- K3: per-b loglik ----------------
__global__ void k3_loglik() {
    __shared__ float red[8];
    const int b = blockIdx.x;
    const int lane = threadIdx.x & 31;
    const int w0 = threadIdx.x >> 5;
    float v = g_alpha[b * K2ST + threadIdx.x];
    v = warpSumf(v);
    if (lane == 0) red[w0] = v;
    __syncthreads();
    if (threadIdx.x == 0) {
        float s = red[0];
#pragma unroll
        for (int w = 1; w < 8; w++) s += red[w];
        g_part[b] = g_C[b] + logf(s);
    }
}

// ---------------- K4: final sum ----------------
__global__ void k4_sum(float* __restrict__ out) {
    __shared__ float red[8];
    const int lane = threadIdx.x & 31;
    const int w0 = threadIdx.x >> 5;
    float acc = 0.0f;
    for (int idx = threadIdx.x; idx < BATCH; idx += 256) acc += g_part[idx];
    acc = warpSumf(acc);
    if (lane == 0) red[w0] = acc;
    __syncthreads();
    if (threadIdx.x == 0) {
        float s = red[0];
#pragma unroll
        for (int w = 1; w < 8; w++) s += red[w];
        out[0] = s;
    }
}

// ---------------- launch ----------------
extern "C" void kernel_launch(void* const* d_in, const int* in_sizes, int n_in,
                              void* d_out, int out_size) {
    const float* seq     = (const float*)d_in[0];
    const float* probs_w = (const float*)d_in[1];
    const float* probs_x = (const float*)d_in[2];
    const float* w_init  = (const float*)d_in[3];
    const float* x_init  = (const float*)d_in[4];
    const float* probs_y = (const float*)d_in[5];
    const int*   lengths = (const int*)d_in[6];
    const int*   mb      = (const int*)d_in[7];
    float* out = (float*)d_out;

    k0_setup<<<1, 256>>>(probs_y, w_init, x_init);
    for (int tile = 0; tile < NTILES; tile++) {
        k1_emis<<<dim3(BATCH, 2), 256>>>(seq, lengths, mb, tile);
        k1b_maxexp<<<BATCH, 256>>>(lengths, mb, tile);
        k2_fwd<<<BATCH, 256>>>(probs_w, probs_x, lengths, mb, tile);
    }
    k3_loglik<<<BATCH, 256>>>();
    k4_sum<<<1, 256>>>(out);
}

// round 4
// speedup vs baseline: 2.7643x; 1.5629x over previous
#include <cuda_runtime.h>
#include <cuda_fp16.h>
#include <cstdint>
#include <cstddef>

#define D_TONES 88
#define DPAD    104
#define T_LEN   512
#define K2ST    256
#define BATCH   1024
#define TILE_T  64
#define NTILES  8

// ---------------- device scratch ----------------
__device__ __align__(16) __half g_wdh[K2ST * DPAD];     // fp16 weights [k][d]
__device__ float g_cst[K2ST];                           // sum_d log1mp
__device__ float g_a0[K2ST];                            // linear init w_init*x_init
__device__ float g_logB[(size_t)BATCH * TILE_T * K2ST]; // logB, then E in place (64MB, L2)
__device__ float g_msum[BATCH];                         // per-tile sum of row maxes
__device__ unsigned g_alpha_h[BATCH * 128];             // fp16x2 A-fragment carry (4 u32/lane)
__device__ float g_C[BATCH];
__device__ float g_part[BATCH];

// ---------------- helpers ----------------
__device__ __forceinline__ float warpMaxf(float v) {
#pragma unroll
    for (int s = 16; s > 0; s >>= 1) v = fmaxf(v, __shfl_xor_sync(0xffffffffu, v, s));
    return v;
}
__device__ __forceinline__ float warpSumf(float v) {
#pragma unroll
    for (int s = 16; s > 0; s >>= 1) v += __shfl_xor_sync(0xffffffffu, v, s);
    return v;
}
__device__ __forceinline__ unsigned smem_u32(const void* p) {
    return (unsigned)__cvta_generic_to_shared(p);
}
__device__ __forceinline__ unsigned packh2(float lo, float hi) {
    __half2 h = __floats2half2_rn(lo, hi);
    return *reinterpret_cast<unsigned*>(&h);
}
__device__ __forceinline__ unsigned movmT(unsigned s) {
    unsigned d;
    asm("movmatrix.sync.aligned.m8n8.trans.b16 %0,%1;" : "=r"(d) : "r"(s));
    return d;
}
__device__ __forceinline__ void mma16816(float d[4], const unsigned a[4],
                                         unsigned b0, unsigned b1) {
    asm volatile("mma.sync.aligned.m16n8k16.row.col.f32.f16.f16.f32 "
                 "{%0,%1,%2,%3},{%4,%5,%6,%7},{%8,%9},{%10,%11,%12,%13};"
                 : "=f"(d[0]), "=f"(d[1]), "=f"(d[2]), "=f"(d[3])
                 : "r"(a[0]), "r"(a[1]), "r"(a[2]), "r"(a[3]), "r"(b0), "r"(b1),
                   "f"(0.0f), "f"(0.0f), "f"(0.0f), "f"(0.0f));
}
// E gather in the orientation of the step's output fragment
__device__ __forceinline__ void loadE(float e[8], const float* __restrict__ r,
                                      bool tr, int bn, int bt) {
    if (!tr) {
        float2 p0 = *reinterpret_cast<const float2*>(r + bn);
        float2 p1 = *reinterpret_cast<const float2*>(r + bn + 128);
        float2 p2 = *reinterpret_cast<const float2*>(r + bn + 8);
        float2 p3 = *reinterpret_cast<const float2*>(r + bn + 136);
        e[0] = p0.x; e[1] = p0.y; e[2] = p1.x; e[3] = p1.y;
        e[4] = p2.x; e[5] = p2.y; e[6] = p3.x; e[7] = p3.y;
    } else {
        e[0] = r[bt];       e[1] = r[bt + 16];  e[2] = r[bt + 8];   e[3] = r[bt + 24];
        e[4] = r[bt + 128]; e[5] = r[bt + 144]; e[6] = r[bt + 136]; e[7] = r[bt + 152];
    }
}

// ---------------- K0: precompute ----------------
__global__ void k0_setup(const float* __restrict__ probs_y,
                         const float* __restrict__ w_init,
                         const float* __restrict__ x_init) {
    int k = threadIdx.x;  // 256
    float cs = 0.0f;
    for (int d = 0; d < DPAD; d++) {
        float w = 0.0f;
        if (d < D_TONES) {
            float py = probs_y[k * D_TONES + d];
            float l1 = log1pf(-py);
            w = logf(py) - l1;
            cs += l1;
        }
        g_wdh[k * DPAD + d] = __float2half_rn(w);
    }
    g_cst[k] = cs;
    g_a0[k] = w_init[k >> 4] * x_init[k & 15];
}

// ---------------- K1: emission GEMM via mma.sync (64t x 128k per block) ----------------
__global__ void __launch_bounds__(256) k1_emis(const float* __restrict__ seq,
                                               const int* __restrict__ lengths,
                                               const int* __restrict__ mb,
                                               int tile) {
    const int b   = blockIdx.x;
    const int nh2 = blockIdx.y;
    const int t0  = tile * TILE_T;
    const int row = __ldg(&mb[b]);
    const int len = __ldg(&lengths[row]);
    if (t0 >= len) return;

    __shared__ __align__(16) __half Asm[TILE_T][DPAD];
    __shared__ __align__(16) __half Bsm[128][DPAD];

    const int tid = threadIdx.x;
    const uint4* wp = reinterpret_cast<const uint4*>(g_wdh + (size_t)nh2 * 128 * DPAD);
    for (int idx = tid; idx < 128 * 13; idx += 256)
        reinterpret_cast<uint4*>(&Bsm[0][0])[idx] = __ldg(&wp[idx]);
    for (int idx = tid; idx < TILE_T * 2; idx += 256) {
        int r = idx >> 1, q = idx & 1;
        *reinterpret_cast<uint4*>(&Asm[r][88 + q * 8]) = make_uint4(0, 0, 0, 0);
    }
    const float4* sp = reinterpret_cast<const float4*>(seq + ((size_t)row * T_LEN + t0) * D_TONES);
    for (int idx = tid; idx < TILE_T * 22; idx += 256) {
        int r = idx / 22, c4 = idx % 22;
        float4 v = __ldg(&sp[(size_t)r * 22 + c4]);
        __half2 h0 = __floats2half2_rn(v.x, v.y);
        __half2 h1 = __floats2half2_rn(v.z, v.w);
        uint2 u;
        u.x = *reinterpret_cast<unsigned*>(&h0);
        u.y = *reinterpret_cast<unsigned*>(&h1);
        *reinterpret_cast<uint2*>(&Asm[r][c4 * 4]) = u;
    }
    __syncthreads();

    const int w = tid >> 5, lane = tid & 31;
    const int mt = w & 3;
    const int nh = (w >> 2) * 64;

    float c[8][4];
#pragma unroll
    for (int q = 0; q < 8; q++) { c[q][0] = c[q][1] = c[q][2] = c[q][3] = 0.0f; }

    const unsigned aBase = smem_u32(&Asm[mt * 16 + (lane & 15)][(lane >> 4) * 8]);
    const unsigned bBase = smem_u32(&Bsm[nh + ((lane >> 4) * 8) + (lane & 7)][((lane >> 3) & 1) * 8]);

#pragma unroll
    for (int ks = 0; ks < 6; ks++) {
        unsigned a0, a1, a2, a3;
        asm volatile("ldmatrix.sync.aligned.m8n8.x4.shared.b16 {%0,%1,%2,%3},[%4];"
                     : "=r"(a0), "=r"(a1), "=r"(a2), "=r"(a3) : "r"(aBase + ks * 32));
#pragma unroll
        for (int nt2 = 0; nt2 < 4; nt2++) {
            unsigned b0, b1, b2, b3;
            asm volatile("ldmatrix.sync.aligned.m8n8.x4.shared.b16 {%0,%1,%2,%3},[%4];"
                         : "=r"(b0), "=r"(b1), "=r"(b2), "=r"(b3)
                         : "r"(bBase + nt2 * (16 * DPAD * 2) + ks * 32));
            asm volatile("mma.sync.aligned.m16n8k16.row.col.f32.f16.f16.f32 "
                         "{%0,%1,%2,%3},{%4,%5,%6,%7},{%8,%9},{%0,%1,%2,%3};"
                         : "+f"(c[nt2 * 2][0]), "+f"(c[nt2 * 2][1]),
                           "+f"(c[nt2 * 2][2]), "+f"(c[nt2 * 2][3])
                         : "r"(a0), "r"(a1), "r"(a2), "r"(a3), "r"(b0), "r"(b1));
            asm volatile("mma.sync.aligned.m16n8k16.row.col.f32.f16.f16.f32 "
                         "{%0,%1,%2,%3},{%4,%5,%6,%7},{%8,%9},{%0,%1,%2,%3};"
                         : "+f"(c[nt2 * 2 + 1][0]), "+f"(c[nt2 * 2 + 1][1]),
                           "+f"(c[nt2 * 2 + 1][2]), "+f"(c[nt2 * 2 + 1][3])
                         : "r"(a0), "r"(a1), "r"(a2), "r"(a3), "r"(b2), "r"(b3));
        }
    }

    const int r0 = mt * 16 + (lane >> 2);
    const int cb = nh2 * 128 + nh;
    const int cl = 2 * (lane & 3);
    const size_t ro0 = ((size_t)b * TILE_T + r0) * K2ST;
    const size_t ro1 = ro0 + 8 * K2ST;
#pragma unroll
    for (int q = 0; q < 8; q++) {
        int colg = cb + q * 8 + cl;
        float2 cst2 = *reinterpret_cast<const float2*>(&g_cst[colg]);
        float2 o0 = make_float2(c[q][0] + cst2.x, c[q][1] + cst2.y);
        float2 o1 = make_float2(c[q][2] + cst2.x, c[q][3] + cst2.y);
        *reinterpret_cast<float2*>(&g_logB[ro0 + colg]) = o0;
        *reinterpret_cast<float2*>(&g_logB[ro1 + colg]) = o1;
    }
}

// ---------------- K1b: row max + in-place E=exp(logB-m) + tile sum of m ----------------
__global__ void __launch_bounds__(256) k1b_maxexp(const int* __restrict__ lengths,
                                                  const int* __restrict__ mb, int tile) {
    const int b = blockIdx.x;
    const int t0 = tile * TILE_T;
    const int len = __ldg(&lengths[__ldg(&mb[b])]);
    if (t0 >= len) return;
    __shared__ float m_sh[TILE_T];
    const int wid = threadIdx.x >> 5, lane = threadIdx.x & 31;
#pragma unroll
    for (int it = 0; it < 8; it++) {
        int t = wid * 8 + it;
        float* p = g_logB + ((size_t)b * TILE_T + t) * K2ST;
        float v[8];
#pragma unroll
        for (int q = 0; q < 8; q++) v[q] = p[lane + 32 * q];
        float mx = v[0];
#pragma unroll
        for (int q = 1; q < 8; q++) mx = fmaxf(mx, v[q]);
        mx = warpMaxf(mx);
#pragma unroll
        for (int q = 0; q < 8; q++) p[lane + 32 * q] = __expf(v[q] - mx);
        if (lane == 0) m_sh[t] = mx;
    }
    __syncthreads();
    if (threadIdx.x < 32) {
        int end = min(TILE_T, len - t0);
        float s = (lane < end ? m_sh[lane] : 0.0f) +
                  (32 + lane < end ? m_sh[32 + lane] : 0.0f);
        s = warpSumf(s);
        if (lane == 0) g_msum[b] = s;
    }
}

// ---------------- K2: tensor-core forward recursion, warp per batch element ----------------
// Z alternates orientation each step: even t -> A (normal), odd t -> A^T.
//   t odd : U = Z*X, V = (U^T)*W = A'^T    (E indexed transposed)
//   t even: U = Z*W, V = (U^T)*X = A''     (E indexed normal)
// Renorm every step in f32 keeps fp16 carry safe (E row max == 1).
__global__ void __launch_bounds__(256) k2_fwd(const float* __restrict__ probs_w,
                                              const float* __restrict__ probs_x,
                                              const int* __restrict__ lengths,
                                              const int* __restrict__ mb,
                                              int tile) {
    const int wid = threadIdx.x >> 5, lane = threadIdx.x & 31;
    const int b = blockIdx.x * 8 + wid;
    const int t0 = tile * TILE_T;
    const int len = __ldg(&lengths[__ldg(&mb[b])]);
    if (t0 >= len) return;

    const int g = lane >> 2, t4 = lane & 3;

    // constant B-fragments (fp16): reg0 = {M[2t4][n], M[2t4+1][n]}, reg1 = rows +8
    unsigned Xf00 = packh2(__ldg(&probs_x[(2 * t4) * 16 + g]),     __ldg(&probs_x[(2 * t4 + 1) * 16 + g]));
    unsigned Xf01 = packh2(__ldg(&probs_x[(2 * t4 + 8) * 16 + g]), __ldg(&probs_x[(2 * t4 + 9) * 16 + g]));
    unsigned Xf10 = packh2(__ldg(&probs_x[(2 * t4) * 16 + g + 8]),     __ldg(&probs_x[(2 * t4 + 1) * 16 + g + 8]));
    unsigned Xf11 = packh2(__ldg(&probs_x[(2 * t4 + 8) * 16 + g + 8]), __ldg(&probs_x[(2 * t4 + 9) * 16 + g + 8]));
    unsigned Wf00 = packh2(__ldg(&probs_w[(2 * t4) * 16 + g]),     __ldg(&probs_w[(2 * t4 + 1) * 16 + g]));
    unsigned Wf01 = packh2(__ldg(&probs_w[(2 * t4 + 8) * 16 + g]), __ldg(&probs_w[(2 * t4 + 9) * 16 + g]));
    unsigned Wf10 = packh2(__ldg(&probs_w[(2 * t4) * 16 + g + 8]),     __ldg(&probs_w[(2 * t4 + 1) * 16 + g + 8]));
    unsigned Wf11 = packh2(__ldg(&probs_w[(2 * t4 + 8) * 16 + g + 8]), __ldg(&probs_w[(2 * t4 + 9) * 16 + g + 8]));

    const float* lb = g_logB + (size_t)b * TILE_T * K2ST;
    const int bn = 16 * g + 2 * t4;   // normal-orientation E base
    const int bt = 32 * t4 + g;       // transposed-orientation E base

    unsigned Z[4];
    float C;
    int tl_start;
    if (tile == 0) {
        // t=0: Z = a0 * E0 (normal orientation)
        float2 a00 = *reinterpret_cast<const float2*>(g_a0 + bn);
        float2 a01 = *reinterpret_cast<const float2*>(g_a0 + bn + 128);
        float2 a02 = *reinterpret_cast<const float2*>(g_a0 + bn + 8);
        float2 a03 = *reinterpret_cast<const float2*>(g_a0 + bn + 136);
        float2 e00 = *reinterpret_cast<const float2*>(lb + bn);
        float2 e01 = *reinterpret_cast<const float2*>(lb + bn + 128);
        float2 e02 = *reinterpret_cast<const float2*>(lb + bn + 8);
        float2 e03 = *reinterpret_cast<const float2*>(lb + bn + 136);
        Z[0] = packh2(a00.x * e00.x, a00.y * e00.y);
        Z[1] = packh2(a01.x * e01.x, a01.y * e01.y);
        Z[2] = packh2(a02.x * e02.x, a02.y * e02.y);
        Z[3] = packh2(a03.x * e03.x, a03.y * e03.y);
        C = g_msum[b];
        tl_start = 1;
    } else {
        uint4 z4 = *reinterpret_cast<const uint4*>(&g_alpha_h[(size_t)b * 128 + lane * 4]);
        Z[0] = z4.x; Z[1] = z4.y; Z[2] = z4.z; Z[3] = z4.w;
        C = g_C[b] + g_msum[b];
        tl_start = 0;
    }

    const int tl_end = min(TILE_T, len - t0);
    float ecur[8];
    loadE(ecur, lb + (size_t)tl_start * K2ST, (tl_start & 1) != 0, bn, bt);

    for (int tl = tl_start; tl < tl_end; ++tl) {
        const bool tr = (tl & 1) != 0;     // t0 is even -> parity of t == parity of tl
        // prefetch next step's E (hides L2 latency behind the mma chain)
        float enx[8] = {0, 0, 0, 0, 0, 0, 0, 0};
        if (tl + 1 < tl_end) loadE(enx, lb + (size_t)(tl + 1) * K2ST, !tr, bn, bt);

        unsigned M00, M01, M10, M11, N00, N01, N10, N11;
        if (tr) { M00 = Xf00; M01 = Xf01; M10 = Xf10; M11 = Xf11;
                  N00 = Wf00; N01 = Wf01; N10 = Wf10; N11 = Wf11; }
        else    { M00 = Wf00; M01 = Wf01; M10 = Wf10; M11 = Wf11;
                  N00 = Xf00; N01 = Xf01; N10 = Xf10; N11 = Xf11; }

        float U0[4], U1[4];
        mma16816(U0, Z, M00, M01);
        mma16816(U1, Z, M10, M11);

        unsigned h0 = packh2(U0[0], U0[1]);
        unsigned h1 = packh2(U0[2], U0[3]);
        unsigned h2 = packh2(U1[0], U1[1]);
        unsigned h3 = packh2(U1[2], U1[3]);
        unsigned Zt[4];
        Zt[0] = movmT(h0); Zt[1] = movmT(h2); Zt[2] = movmT(h1); Zt[3] = movmT(h3);

        float V0[4], V1[4];
        mma16816(V0, Zt, N00, N01);
        mma16816(V1, Zt, N10, N11);

#pragma unroll
        for (int q = 0; q < 4; q++) { V0[q] *= ecur[q]; V1[q] *= ecur[4 + q]; }

        // per-step renorm (f32) -> fp16-safe carry
        float s = ((V0[0] + V0[1]) + (V0[2] + V0[3])) + ((V1[0] + V1[1]) + (V1[2] + V1[3]));
        s = warpSumf(s);
        float rcp = __fdividef(1.0f, s);
        C += __logf(s);

        Z[0] = packh2(V0[0] * rcp, V0[1] * rcp);
        Z[1] = packh2(V0[2] * rcp, V0[3] * rcp);
        Z[2] = packh2(V1[0] * rcp, V1[1] * rcp);
        Z[3] = packh2(V1[2] * rcp, V1[3] * rcp);

#pragma unroll
        for (int q = 0; q < 8; q++) ecur[q] = enx[q];
    }

    *reinterpret_cast<uint4*>(&g_alpha_h[(size_t)b * 128 + lane * 4]) =
        make_uint4(Z[0], Z[1], Z[2], Z[3]);
    if (lane == 0) g_C[b] = C;
}

// ---------------- K3: per-b loglik (sum of fp16 alpha fragments) ----------------
__global__ void k3_loglik() {   // grid=BATCH, 32 threads
    const int b = blockIdx.x, lane = threadIdx.x;
    uint4 z = *reinterpret_cast<const uint4*>(&g_alpha_h[(size_t)b * 128 + lane * 4]);
    float2 f0 = __half22float2(*reinterpret_cast<__half2*>(&z.x));
    float2 f1 = __half22float2(*reinterpret_cast<__half2*>(&z.y));
    float2 f2 = __half22float2(*reinterpret_cast<__half2*>(&z.z));
    float2 f3 = __half22float2(*reinterpret_cast<__half2*>(&z.w));
    float s = ((f0.x + f0.y) + (f1.x + f1.y)) + ((f2.x + f2.y) + (f3.x + f3.y));
    s = warpSumf(s);
    if (lane == 0) g_part[b] = g_C[b] + logf(s);
}

// ---------------- K4: final sum ----------------
__global__ void k4_sum(float* __restrict__ out) {
    __shared__ float red[8];
    const int lane = threadIdx.x & 31;
    const int w0 = threadIdx.x >> 5;
    float acc = 0.0f;
    for (int idx = threadIdx.x; idx < BATCH; idx += 256) acc += g_part[idx];
    acc = warpSumf(acc);
    if (lane == 0) red[w0] = acc;
    __syncthreads();
    if (threadIdx.x == 0) {
        float s = red[0];
#pragma unroll
        for (int w = 1; w < 8; w++) s += red[w];
        out[0] = s;
    }
}

// ---------------- launch ----------------
extern "C" void kernel_launch(void* const* d_in, const int* in_sizes, int n_in,
                              void* d_out, int out_size) {
    const float* seq     = (const float*)d_in[0];
    const float* probs_w = (const float*)d_in[1];
    const float* probs_x = (const float*)d_in[2];
    const float* w_init  = (const float*)d_in[3];
    const float* x_init  = (const float*)d_in[4];
    const float* probs_y = (const float*)d_in[5];
    const int*   lengths = (const int*)d_in[6];
    const int*   mb      = (const int*)d_in[7];
    float* out = (float*)d_out;

    k0_setup<<<1, 256>>>(probs_y, w_init, x_init);
    for (int tile = 0; tile < NTILES; tile++) {
        k1_emis<<<dim3(BATCH, 2), 256>>>(seq, lengths, mb, tile);
        k1b_maxexp<<<BATCH, 256>>>(lengths, mb, tile);
        k2_fwd<<<BATCH / 8, 256>>>(probs_w, probs_x, lengths, mb, tile);
    }
    k3_loglik<<<BATCH, 32>>>();
    k4_sum<<<1, 256>>>(out);
}